// round 15
// baseline (speedup 1.0000x reference)
#include <cuda_runtime.h>
#include <cuda_bf16.h>
#include <cstdint>

#define MROWS   512   // rows of weight / output dim
#define KDIM    20    // motion dim
#define OUT_DIM 512
#define TILE_M  128   // batch rows per tile
#define KPAD    64    // split-K layout: A=[hi20|lo20|hi20|0], B=[hi20|hi20|lo20|0]
#define GTHREADS 256  // 8 warps, each owns 64 output cols
#define SROW_W  36    // A smem row stride in words -> conflict-free LDSM phases
#define GRID_P  296   // persistent: 2 CTAs/SM

// B' table (bf16): g_Qbf[n*64 + k]; k 0-19 = Qhi, 20-39 = Qhi, 40-59 = Qlo, 60-63 = 0
__device__ __align__(16) __nv_bfloat16 g_Qbf[OUT_DIM * KPAD];

// ---------------------------------------------------------------------------
// helpers
// ---------------------------------------------------------------------------
__device__ __forceinline__ uint32_t bf2pack(float a, float b) {
    __nv_bfloat162 t = __floats2bfloat162_rn(a, b);
    return *reinterpret_cast<uint32_t*>(&t);
}

__device__ __forceinline__ float blockReduceSum(float x, float* red) {
    int lane = threadIdx.x & 31;
    int wid  = threadIdx.x >> 5;
    #pragma unroll
    for (int off = 16; off; off >>= 1) x += __shfl_xor_sync(0xffffffffu, x, off);
    if (lane == 0) red[wid] = x;
    __syncthreads();
    float s = (lane < 16) ? red[lane] : 0.f;
    #pragma unroll
    for (int off = 8; off; off >>= 1) s += __shfl_xor_sync(0xffffffffu, s, off);
    s = __shfl_sync(0xffffffffu, s, 0);
    __syncthreads();
    return s;
}

__device__ __forceinline__ void mma16816(float* d,
                                         uint32_t a0, uint32_t a1, uint32_t a2, uint32_t a3,
                                         uint32_t b0, uint32_t b1) {
    asm("mma.sync.aligned.m16n8k16.row.col.f32.bf16.bf16.f32 "
        "{%0,%1,%2,%3}, {%4,%5,%6,%7}, {%8,%9}, {%0,%1,%2,%3};"
        : "+f"(d[0]), "+f"(d[1]), "+f"(d[2]), "+f"(d[3])
        : "r"(a0), "r"(a1), "r"(a2), "r"(a3), "r"(b0), "r"(b1));
}

__device__ __forceinline__ void ldsm_x4(uint32_t* r, uint32_t addr) {
    asm volatile("ldmatrix.sync.aligned.m8n8.x4.shared.b16 {%0,%1,%2,%3}, [%4];"
                 : "=r"(r[0]), "=r"(r[1]), "=r"(r[2]), "=r"(r[3]) : "r"(addr));
}

__device__ __forceinline__ void stg_cs_v4(float* p, float4 v) {
    asm volatile("st.global.cs.v4.f32 [%0], {%1, %2, %3, %4};"
                 :: "l"(p), "f"(v.x), "f"(v.y), "f"(v.z), "f"(v.w) : "memory");
}

// ---------------------------------------------------------------------------
// QR of W + 1e-8 (W: [512,20]) with LAPACK geqr2 signs, WITHOUT org2r:
//   geqr2 -> R; Rinv by back-substitution; Q = (W+1e-8) * Rinv.
// Emits bf16 hi/lo split table g_Qbf (B layout: [qh|qh|ql|0]).
// ---------------------------------------------------------------------------
__global__ void qr_kernel(const float* __restrict__ W) {
    __shared__ float sA[KDIM][MROWS];    // column-major: sA[c][t] = A[t][c]
    __shared__ float sV[MROWS];
    __shared__ float sRinv[KDIM][KDIM + 1];
    __shared__ float sRed[16];

    const int t    = threadIdx.x;
    const int lane = t & 31;
    const int wid  = t >> 5;

    float wrow[KDIM];                    // this thread's row of W + 1e-8
    #pragma unroll
    for (int c = 0; c < KDIM; ++c) {
        wrow[c] = W[t * KDIM + c] + 1e-8f;
        sA[c][t] = wrow[c];
    }
    __syncthreads();

    // ---- geqr2 ----
    for (int j = 0; j < KDIM; ++j) {
        float a  = sA[j][t];
        float sq = (t > j) ? a * a : 0.f;
        float xnorm2 = blockReduceSum(sq, sRed);
        float alpha  = sA[j][j];
        float beta   = -copysignf(sqrtf(alpha * alpha + xnorm2), alpha);  // LAPACK sign
        float tau    = (beta - alpha) / beta;
        float inv    = 1.f / (alpha - beta);
        float v      = (t == j) ? 1.f : ((t > j) ? a * inv : 0.f);
        sV[t] = v;
        if (t == j) sA[j][j] = beta;     // R diagonal
        __syncthreads();

        for (int c = j + 1 + wid; c < KDIM; c += 16) {
            float w = 0.f;
            #pragma unroll
            for (int i = lane; i < MROWS; i += 32) w += sV[i] * sA[c][i];
            #pragma unroll
            for (int off = 16; off; off >>= 1) w += __shfl_xor_sync(0xffffffffu, w, off);
            float tw = tau * w;
            #pragma unroll
            for (int i = lane; i < MROWS; i += 32) sA[c][i] -= tw * sV[i];
        }
        __syncthreads();
    }

    // ---- Rinv: thread c solves R x = e_c ----
    if (t < KDIM) {
        const int c = t;
        float x[KDIM];
        #pragma unroll
        for (int i = 0; i < KDIM; ++i) x[i] = 0.f;
        x[c] = 1.f / sA[c][c];
        for (int i = c - 1; i >= 0; --i) {
            float s = 0.f;
            for (int k = i + 1; k <= c; ++k) s += sA[k][i] * x[k];
            x[i] = -s / sA[i][i];
        }
        #pragma unroll
        for (int k = 0; k < KDIM; ++k) sRinv[k][c] = x[k];
    }
    __syncthreads();

    // ---- Q row t = wrow * Rinv; bf16 hi/lo split -> g_Qbf ----
    #pragma unroll
    for (int c = 0; c < KDIM; ++c) {
        float q = 0.f;
        for (int k = 0; k <= c; ++k) q += wrow[k] * sRinv[k][c];
        __nv_bfloat16 h = __float2bfloat16_rn(q);
        float lo = q - __bfloat162float(h);
        g_Qbf[t * KPAD + c]            = h;
        g_Qbf[t * KPAD + KDIM + c]     = h;
        g_Qbf[t * KPAD + 2 * KDIM + c] = __float2bfloat16_rn(lo);
    }
    #pragma unroll
    for (int k = 3 * KDIM; k < KPAD; ++k)
        g_Qbf[t * KPAD + k] = __float2bfloat16_rn(0.f);
}

// ---------------------------------------------------------------------------
// Persistent HMMA GEMM with PERMUTED N-mapping for v4 stores.
// MMA col c (0..7) of tile j (0..7) holds output col
//     n_out = wid*64 + 16*(j>>1) + 4*(c>>1) + 2*(j&1) + (c&1)
// => d cols {2cq, 2cq+1} of tiles 2m/2m+1 are output cols 16m+4cq .. +3,
// so each thread stores ONE st.cs.v4 per (row, m). Bijective over 64 cols.
// Everything else identical to the R8/R13 gemm.
// ---------------------------------------------------------------------------
__global__ void __launch_bounds__(GTHREADS, 2)
gemm_hmma_kernel(const float* __restrict__ input, float* __restrict__ out,
                 int batch, int ntiles) {
    __shared__ uint32_t sW[2][TILE_M * SROW_W];   // 2 x 18432 B

    const int tid  = threadIdx.x;
    const int wid  = tid >> 5;
    const int lane = tid & 31;
    const int g    = lane >> 2;        // fragment row group 0..7
    const int cq   = lane & 3;         // quad col

    // ---- B fragments (once per block), permuted mapping ----
    // B fragment of tile j: thread (g,cq) supplies b[k=2cq+8t][n=c] with c=g.
    uint32_t Bf[8][8];
    {
        const uint32_t* qw = reinterpret_cast<const uint32_t*>(g_Qbf);
        #pragma unroll
        for (int j = 0; j < 8; ++j) {
            const int c = g;
            const int n_out = wid * 64 + 16 * (j >> 1) + 4 * (c >> 1) + 2 * (j & 1) + (c & 1);
            const uint32_t* qrow = qw + n_out * (KPAD / 2) + cq;
            #pragma unroll
            for (int t = 0; t < 8; ++t)
                Bf[j][t] = qrow[4 * t];
        }
    }

    // ---- conversion: tile tt -> buffer buf ----
    auto convert_tile = [&](long long tt, int buf) {
        const int r = tid >> 1;                 // row 0..127
        const int h = tid & 1;                  // half: k0 = 10h
        const long long grow = tt * TILE_M + r;
        float2 v[5];
        if (grow < batch) {
            const float2* src = reinterpret_cast<const float2*>(input + grow * KDIM + 10 * h);
            #pragma unroll
            for (int p = 0; p < 5; ++p) v[p] = src[p];
        } else {
            #pragma unroll
            for (int p = 0; p < 5; ++p) v[p] = make_float2(0.f, 0.f);
        }
        uint32_t* row = sW[buf] + r * SROW_W;
        #pragma unroll
        for (int p = 0; p < 5; ++p) {
            const int k = 10 * h + 2 * p;
            float x0 = v[p].x, x1 = v[p].y;
            __nv_bfloat16 h0 = __float2bfloat16_rn(x0);
            __nv_bfloat16 h1 = __float2bfloat16_rn(x1);
            uint32_t hp = bf2pack(x0, x1);
            uint32_t lp = bf2pack(x0 - __bfloat162float(h0), x1 - __bfloat162float(h1));
            row[k / 2]      = hp;   // hi block
            row[10 + k / 2] = lp;   // lo block
            row[20 + k / 2] = hp;   // hi dup
        }
        if (h) { row[30] = 0u; row[31] = 0u; }   // k 60..63 = 0
    };

    // ldmatrix lane address base
    const uint32_t smem0 = (uint32_t)__cvta_generic_to_shared(&sW[0][0]);
    const uint32_t smem1 = (uint32_t)__cvta_generic_to_shared(&sW[1][0]);
    const uint32_t lane_off = (((lane & 15) * SROW_W + ((lane & 16) ? 4 : 0)) * 4);

    const int colbase = wid * 64 + 4 * cq;    // v4 base within each 16-col group
    const long long stride = gridDim.x;
    const long long t0 = blockIdx.x;

    if (t0 < ntiles) convert_tile(t0, 0);
    __syncthreads();

    int buf = 0;
    for (long long t = t0; t < ntiles; t += stride) {
        const long long tn = t + stride;
        if (tn < ntiles) convert_tile(tn, buf ^ 1);

        const long long tb = t * TILE_M;
        const uint32_t sbase = (buf ? smem1 : smem0) + lane_off;

        #pragma unroll 1
        for (int ms = 0; ms < 8; ++ms) {
            const uint32_t mbase = sbase + (uint32_t)(16 * ms * SROW_W * 4);

            float acc[8][4];
            #pragma unroll
            for (int j = 0; j < 8; ++j)
                acc[j][0] = acc[j][1] = acc[j][2] = acc[j][3] = 0.f;

            #pragma unroll
            for (int s = 0; s < 4; ++s) {
                uint32_t a[4];
                ldsm_x4(a, mbase + 32u * s);
                #pragma unroll
                for (int j = 0; j < 8; ++j)
                    mma16816(acc[j], a[0], a[1], a[2], a[3],
                             Bf[j][2 * s], Bf[j][2 * s + 1]);
            }

            // stores: tiles 2m/2m+1 -> one v4 at col 16m + 4cq
            const long long grow0 = tb + 16 * ms + g;
            if (grow0 < batch) {
                float* p0 = out + grow0 * OUT_DIM + colbase;
                #pragma unroll
                for (int m = 0; m < 4; ++m)
                    stg_cs_v4(p0 + 16 * m,
                              make_float4(acc[2 * m][0], acc[2 * m][1],
                                          acc[2 * m + 1][0], acc[2 * m + 1][1]));
            }
            if (grow0 + 8 < batch) {
                float* p1 = out + (grow0 + 8) * OUT_DIM + colbase;
                #pragma unroll
                for (int m = 0; m < 4; ++m)
                    stg_cs_v4(p1 + 16 * m,
                              make_float4(acc[2 * m][2], acc[2 * m][3],
                                          acc[2 * m + 1][2], acc[2 * m + 1][3]));
            }
        }

        __syncthreads();
        buf ^= 1;
    }
}

// ---------------------------------------------------------------------------
extern "C" void kernel_launch(void* const* d_in, const int* in_sizes, int n_in,
                              void* d_out, int out_size) {
    const float* input  = (const float*)d_in[0];
    const float* weight = (const float*)d_in[1];
    int s0 = in_sizes[0], s1 = in_sizes[1];
    if (s0 < s1) {
        const float* tmp = input; input = weight; weight = tmp;
        int ts = s0; s0 = s1; s1 = ts;
    }
    const int batch  = s0 / KDIM;
    const int ntiles = (batch + TILE_M - 1) / TILE_M;

    qr_kernel<<<1, MROWS>>>(weight);
    gemm_hmma_kernel<<<GRID_P, GTHREADS>>>(input, (float*)d_out, batch, ntiles);
}